// round 8
// baseline (speedup 1.0000x reference)
#include <cuda_runtime.h>
#include <stdint.h>

#define TPB 128
#define KD(x) ((double)((unsigned long long)(x) << 24))

// K constants pre-scaled to 2^-24 units (exact: 32 significant bits)
__constant__ double cKd[64] = {
    KD(0xd76aa478u),KD(0xe8c7b756u),KD(0x242070dbu),KD(0xc1bdceeeu),
    KD(0xf57c0fafu),KD(0x4787c62au),KD(0xa8304613u),KD(0xfd469501u),
    KD(0x698098d8u),KD(0x8b44f7afu),KD(0xffff5bb1u),KD(0x895cd7beu),
    KD(0x6b901122u),KD(0xfd987193u),KD(0xa679438eu),KD(0x49b40821u),
    KD(0xf61e2562u),KD(0xc040b340u),KD(0x265e5a51u),KD(0xe9b6c7aau),
    KD(0xd62f105du),KD(0x02441453u),KD(0xd8a1e681u),KD(0xe7d3fbc8u),
    KD(0x21e1cde6u),KD(0xc33707d6u),KD(0xf4d50d87u),KD(0x455a14edu),
    KD(0xa9e3e905u),KD(0xfcefa3f8u),KD(0x676f02d9u),KD(0x8d2a4c8au),
    KD(0xfffa3942u),KD(0x8771f681u),KD(0x6d9d6122u),KD(0xfde5380cu),
    KD(0xa4beea44u),KD(0x4bdecfa9u),KD(0xf6bb4b60u),KD(0xbebfbc70u),
    KD(0x289b7ec6u),KD(0xeaa127fau),KD(0xd4ef3085u),KD(0x04881d05u),
    KD(0xd9d4d039u),KD(0xe6db99e5u),KD(0x1fa27cf8u),KD(0xc4ac5665u),
    KD(0xf4292244u),KD(0x432aff97u),KD(0xab9423a7u),KD(0xfc93a039u),
    KD(0x655b59c3u),KD(0x8f0ccc92u),KD(0xffeff47du),KD(0x85845dd1u),
    KD(0x6fa87e4fu),KD(0xfe2ce6e0u),KD(0xa3014314u),KD(0x4e0811a1u),
    KD(0xf7537e82u),KD(0xbd3af235u),KD(0x2ad7d2bbu),KD(0xeb86d391u) };

__constant__ uint32_t cK[64] = {
    0xd76aa478u,0xe8c7b756u,0x242070dbu,0xc1bdceeeu,
    0xf57c0fafu,0x4787c62au,0xa8304613u,0xfd469501u,
    0x698098d8u,0x8b44f7afu,0xffff5bb1u,0x895cd7beu,
    0x6b901122u,0xfd987193u,0xa679438eu,0x49b40821u,
    0xf61e2562u,0xc040b340u,0x265e5a51u,0xe9b6c7aau,
    0xd62f105du,0x02441453u,0xd8a1e681u,0xe7d3fbc8u,
    0x21e1cde6u,0xc33707d6u,0xf4d50d87u,0x455a14edu,
    0xa9e3e905u,0xfcefa3f8u,0x676f02d9u,0x8d2a4c8au,
    0xfffa3942u,0x8771f681u,0x6d9d6122u,0xfde5380cu,
    0xa4beea44u,0x4bdecfa9u,0xf6bb4b60u,0xbebfbc70u,
    0x289b7ec6u,0xeaa127fau,0xd4ef3085u,0x04881d05u,
    0xd9d4d039u,0xe6db99e5u,0x1fa27cf8u,0xc4ac5665u,
    0xf4292244u,0x432aff97u,0xab9423a7u,0xfc93a039u,
    0x655b59c3u,0x8f0ccc92u,0xffeff47du,0x85845dd1u,
    0x6fa87e4fu,0xfe2ce6e0u,0xa3014314u,0x4e0811a1u,
    0xf7537e82u,0xbd3af235u,0x2ad7d2bbu,0xeb86d391u };

__constant__ uint8_t cS[64] = {
    7,12,17,22, 7,12,17,22, 7,12,17,22, 7,12,17,22,
    5, 9,14,20, 5, 9,14,20, 5, 9,14,20, 5, 9,14,20,
    4,11,16,23, 4,11,16,23, 4,11,16,23, 4,11,16,23,
    6,10,15,21, 6,10,15,21, 6,10,15,21, 6,10,15,21 };

__constant__ uint8_t cG[64] = {
    0,1,2,3,4,5,6,7,8,9,10,11,12,13,14,15,
    1,6,11,0,5,10,15,4,9,14,3,8,13,2,7,12,
    5,8,11,14,1,4,7,10,13,0,3,6,9,12,15,2,
    0,7,14,5,12,3,10,1,8,15,6,13,4,11,2,9 };

// ---- f32 soft ops, exact IEEE-RN, reference association --------------------
__device__ __forceinline__ float fxor(float a, float b) {
    return __fsub_rn(__fadd_rn(a, b), __fmul_rn(__fmul_rn(2.0f, a), b));
}
__device__ __forceinline__ float fand(float a, float b) { return __fmul_rn(a, b); }
__device__ __forceinline__ float forr(float a, float b) {
    return __fsub_rn(__fadd_rn(a, b), __fmul_rn(a, b));
}
__device__ __forceinline__ float fnot(float a) { return __fsub_rn(1.0f, a); }

// state code: bit0 = hard bit, bit1 = deficit (value 1-2^-24)
__device__ __forceinline__ float decst(int st) {
    if (!(st & 1)) return 0.0f;
    return (st & 2) ? __uint_as_float(0x3F7FFFFFu) : 1.0f;
}
__device__ __forceinline__ float fphase(int ph, float b, float c, float d) {
    if (ph == 0) return forr(fand(b, c), fand(fnot(b), d));
    if (ph == 1) return forr(fand(d, b), fand(fnot(d), c));
    if (ph == 2) return fxor(fxor(b, c), d);
    return fxor(c, forr(b, fnot(d)));
}
// deficit predicate: soft_add32 result bit is (1-2^-24) iff hard=1 AND this
__device__ __forceinline__ uint32_t pbit(float x, float y) {
    float px = __fmul_rn(fxor(x, y), 0.5f);
    float r  = __fsub_rn(__fadd_rn(1.0f, px), px);
    return (__float_as_uint(r) != 0x3F800000u) ? 1u : 0u;
}

// ---- sequential f64 value of a T-valued word, 2^-24 units, as f64 ----------
// Lanes 0..28 exact in u64 -> single exact I2F (RN, but value < 2^53 so exact);
// lanes 29..31: one DADD each == the reference's per-lane RN rounding.
__device__ __forceinline__ double tvald(uint32_t H, uint32_t P) {
    uint64_t E = (((uint64_t)(H & 0x1FFFFFFFu)) << 24) - (uint64_t)(P & 0x1FFFFFFFu);
    double e = __ull2double_rn(E);
#pragma unroll
    for (int i = 29; i < 32; i++) {
        double t = ((H >> i) & 1u)
                 ? (((P >> i) & 1u) ? (double)((1ull << (24 + i)) - (1ull << i))
                                     : (double)(1ull << (24 + i)))
                 : 0.0;
        e = __dadd_rn(e, t);
    }
    return e;
}
// floor(fmod(s, 2^32)) of a units-scale f64 sum (s < 2^57), as hard mask
__device__ __forceinline__ uint32_t floorh(double s) {
    const double C = 72057594037927936.0;           // 2^56 (= 2^32 in units)
    double t = __dsub_rn(s, C);                      // exact when s >= C
    s = (s >= C) ? t : s;
    return (uint32_t)(__double2ull_rz(s) >> 24);     // trunc == floor (s >= 0)
}
// T (+) T soft_add32 on masks (alias-safe)
__device__ __forceinline__ void tadd(uint32_t Hx, uint32_t Px, double vx,
                                     uint32_t Hy, uint32_t Py, double vy,
                                     uint32_t& Ho, uint32_t& Po, double& vo) {
    uint32_t ho = floorh(__dadd_rn(vx, vy));
    uint32_t po = ho & (Hx & Hy & (Px | Py));
    double vv = tvald(ho, po);
    Ho = ho; Po = po; vo = vv;
}

// ---- one MD5 compress over bit-sliced T-state -------------------------------
template<int BLK2>
__device__ void compress_fn(
    uint32_t& Ha, uint32_t& Pa, double& va,
    uint32_t& Hb, uint32_t& Pb, double& vb,
    uint32_t& Hc, uint32_t& Pc, double& vc,
    uint32_t& Hd, uint32_t& Pd, double& vd,
    const uint64_t (*sT)[64],
    const double* wv, const uint32_t* m0, const uint32_t* x1, const uint32_t* x2)
{
#pragma unroll 1
    for (int i = 0; i < 64; i++) {
        const uint64_t* ft = sT[i >> 4];
        double s = 0.0;
        uint32_t pred1 = 0;
#pragma unroll
        for (int j = 0; j < 32; j++) {
            uint32_t idx = ((Hb >> j) & 1u) | (((Pb >> j) & 1u) << 1)
                         | (((Hc >> j) & 1u) << 2) | (((Pc >> j) & 1u) << 3)
                         | (((Hd >> j) & 1u) << 4) | (((Pd >> j) & 1u) << 5);
            uint64_t e = ft[idx];
            // f value (units scale) with pred bits masked out of the mantissa
            double fv = __longlong_as_double((long long)(e & ~15ull));
            // fma(fv, 2^j, s): product exact -> identical to reference RN chain
            s = __fma_rn(fv, (double)(1u << j), s);
            uint32_t ast = ((Ha >> j) & 1u) | (((Pa >> j) & 1u) << 1);
            pred1 |= (((uint32_t)e >> ast) & 1u) << j;
        }
        // add1: f + a   (fine x T)
        uint32_t H1 = floorh(__dadd_rn(s, va));
        uint32_t P1 = H1 & pred1;
        double v1 = tvald(H1, P1);
        // add2: + K[i]  (T x hard)
        uint32_t Km = cK[i];
        uint32_t H2 = floorh(__dadd_rn(v1, cKd[i]));
        uint32_t P2 = H2 & (Km & P1);
        double v2 = tvald(H2, P2);
        // add3: + word[g]
        int g = cG[i];
        uint32_t H3, P3;
        if (BLK2) {
            uint32_t pw = (g == 0) ? 0x80u : ((g == 14) ? 0x200u : 0u);
            double pwd = (g == 0) ? (double)(0x80ull << 24)
                       : ((g == 14) ? (double)(0x200ull << 24) : 0.0);
            H3 = floorh(__dadd_rn(v2, pwd));
            P3 = H3 & (P2 & pw);
        } else {
            H3 = floorh(__dadd_rn(v2, wv[g]));
            uint32_t pr = m0[g] ^ (H2 & x1[g]) ^ (P2 & x2[g]);
            P3 = H3 & pr;
        }
        // rotate, then b = soft_add32(b, rot)
        int sh = cS[i];
        uint32_t H3r = __funnelshift_l(H3, H3, sh);
        uint32_t P3r = __funnelshift_l(P3, P3, sh);
        double v3 = tvald(H3r, P3r);
        uint32_t H4 = floorh(__dadd_rn(vb, v3));
        uint32_t P4 = H4 & (Hb & H3r & (Pb | P3r));
        double v4 = tvald(H4, P4);
        Ha = Hd; Pa = Pd; va = vd;
        Hd = Hc; Pd = Pc; vd = vc;
        Hc = Hb; Pc = Pb; vc = vb;
        Hb = H4; Pb = P4; vb = v4;
    }
}

__global__ void __launch_bounds__(TPB)
softmd5_kernel(const float* __restrict__ in, float* __restrict__ out, int B)
{
    __shared__ uint64_t sT[4][64];   // f64 (units) with 4-bit pred pack in low mantissa

    int t = threadIdx.x;
    const float ONEME = __uint_as_float(0x3F7FFFFFu);
    for (int k = t; k < 256; k += TPB) {
        int ph = k >> 6, idx = k & 63;
        float f = fphase(ph, decst(idx & 3), decst((idx >> 2) & 3), decst((idx >> 4) & 3));
        double fv = __dmul_rn((double)f, 16777216.0);   // exact units scaling
        uint64_t bits = (uint64_t)__double_as_longlong(fv);
        uint32_t pp = pbit(f, 0.0f) | (pbit(f, 1.0f) << 1) | (pbit(f, ONEME) << 3);
        sT[ph][idx] = bits | pp;    // low 29 mantissa bits are zero: safe
    }
    __syncthreads();

    int row = blockIdx.x * TPB + t;
    if (row >= B) return;

    const float4* rp = reinterpret_cast<const float4*>(in + (size_t)row * 512);

    // word values (sequential f64 chain, units scale) + add3 deficit masks
    double   wv[16];
    uint32_t m0[16], x1[16], x2[16];
#pragma unroll 1
    for (int g = 0; g < 16; g++) {
        double s = 0.0;
        uint32_t a0 = 0, a1 = 0, a2 = 0;
        for (int q = 0; q < 8; q++) {
            float4 w4 = rp[g * 8 + q];
            float w[4] = { w4.x, w4.y, w4.z, w4.w };
#pragma unroll
            for (int u = 0; u < 4; u++) {
                int j = q * 4 + u;
                // fma(w, 2^(24+j), s): exact product, one RN == reference
                s = __fma_rn((double)w[u], (double)(1ull << (24 + j)), s);
                a0 |= pbit(0.0f,  w[u]) << j;
                a1 |= pbit(1.0f,  w[u]) << j;
                a2 |= pbit(ONEME, w[u]) << j;
            }
        }
        wv[g] = s; m0[g] = a0; x1[g] = a0 ^ a1; x2[g] = a1 ^ a2;
    }

    // H-state (T-masks + cached f64 value, units scale)
    uint32_t HA = 0x67452301u, PA = 0, HB = 0xefcdab89u, PB = 0;
    uint32_t HC = 0x98badcfeu, PC = 0, HD = 0x10325476u, PD = 0;
    double VA = (double)(0x67452301ull << 24), VB = (double)(0xefcdab89ull << 24);
    double VC = (double)(0x98badcfeull << 24), VD = (double)(0x10325476ull << 24);

    // ---- block 1 ----
    {
        uint32_t ha=HA,pa=PA,hb=HB,pb=PB,hc=HC,pc=PC,hd=HD,pd=PD;
        double va=VA,vb=VB,vc=VC,vd=VD;
        compress_fn<0>(ha,pa,va, hb,pb,vb, hc,pc,vc, hd,pd,vd,
                       sT, wv, m0, x1, x2);
        tadd(HA,PA,VA, ha,pa,va, HA,PA,VA);
        tadd(HB,PB,VB, hb,pb,vb, HB,PB,VB);
        tadd(HC,PC,VC, hc,pc,vc, HC,PC,VC);
        tadd(HD,PD,VD, hd,pd,vd, HD,PD,VD);
    }
    // ---- block 2 (constant padding) ----
    {
        uint32_t ha=HA,pa=PA,hb=HB,pb=PB,hc=HC,pc=PC,hd=HD,pd=PD;
        double va=VA,vb=VB,vc=VC,vd=VD;
        compress_fn<1>(ha,pa,va, hb,pb,vb, hc,pc,vc, hd,pd,vd,
                       sT, wv, m0, x1, x2);
        tadd(HA,PA,VA, ha,pa,va, HA,PA,VA);
        tadd(HB,PB,VB, hb,pb,vb, HB,PB,VB);
        tadd(HC,PC,VC, hc,pc,vc, HC,PC,VC);
        tadd(HD,PD,VD, hd,pd,vd, HD,PD,VD);
    }

    // ---- emit 128 float bits ----
    float4* op = reinterpret_cast<float4*>(out + (size_t)row * 128);
    uint32_t Hs[4] = { HA, HB, HC, HD }, Ps[4] = { PA, PB, PC, PD };
#pragma unroll
    for (int w = 0; w < 4; w++) {
        uint32_t Hm = Hs[w], Pm = Ps[w];
#pragma unroll
        for (int j = 0; j < 32; j += 4) {
            float4 f4;
            f4.x = __uint_as_float(((Hm>>(j+0))&1u) ? (((Pm>>(j+0))&1u)?0x3F7FFFFFu:0x3F800000u) : 0u);
            f4.y = __uint_as_float(((Hm>>(j+1))&1u) ? (((Pm>>(j+1))&1u)?0x3F7FFFFFu:0x3F800000u) : 0u);
            f4.z = __uint_as_float(((Hm>>(j+2))&1u) ? (((Pm>>(j+2))&1u)?0x3F7FFFFFu:0x3F800000u) : 0u);
            f4.w = __uint_as_float(((Hm>>(j+3))&1u) ? (((Pm>>(j+3))&1u)?0x3F7FFFFFu:0x3F800000u) : 0u);
            op[w*8 + (j>>2)] = f4;
        }
    }
}

extern "C" void kernel_launch(void* const* d_in, const int* in_sizes, int n_in,
                              void* d_out, int out_size)
{
    const float* in = (const float*)d_in[0];
    float* out = (float*)d_out;
    int B = in_sizes[0] / 512;            // 131072 rows
    int blocks = (B + TPB - 1) / TPB;
    softmd5_kernel<<<blocks, TPB>>>(in, out, B);
}

// round 9
// speedup vs baseline: 1.6874x; 1.6874x over previous
#include <cuda_runtime.h>
#include <stdint.h>

#define TPB 128

__constant__ uint32_t cK[64] = {
    0xd76aa478u,0xe8c7b756u,0x242070dbu,0xc1bdceeeu,
    0xf57c0fafu,0x4787c62au,0xa8304613u,0xfd469501u,
    0x698098d8u,0x8b44f7afu,0xffff5bb1u,0x895cd7beu,
    0x6b901122u,0xfd987193u,0xa679438eu,0x49b40821u,
    0xf61e2562u,0xc040b340u,0x265e5a51u,0xe9b6c7aau,
    0xd62f105du,0x02441453u,0xd8a1e681u,0xe7d3fbc8u,
    0x21e1cde6u,0xc33707d6u,0xf4d50d87u,0x455a14edu,
    0xa9e3e905u,0xfcefa3f8u,0x676f02d9u,0x8d2a4c8au,
    0xfffa3942u,0x8771f681u,0x6d9d6122u,0xfde5380cu,
    0xa4beea44u,0x4bdecfa9u,0xf6bb4b60u,0xbebfbc70u,
    0x289b7ec6u,0xeaa127fau,0xd4ef3085u,0x04881d05u,
    0xd9d4d039u,0xe6db99e5u,0x1fa27cf8u,0xc4ac5665u,
    0xf4292244u,0x432aff97u,0xab9423a7u,0xfc93a039u,
    0x655b59c3u,0x8f0ccc92u,0xffeff47du,0x85845dd1u,
    0x6fa87e4fu,0xfe2ce6e0u,0xa3014314u,0x4e0811a1u,
    0xf7537e82u,0xbd3af235u,0x2ad7d2bbu,0xeb86d391u };

__constant__ uint8_t cS[64] = {
    7,12,17,22, 7,12,17,22, 7,12,17,22, 7,12,17,22,
    5, 9,14,20, 5, 9,14,20, 5, 9,14,20, 5, 9,14,20,
    4,11,16,23, 4,11,16,23, 4,11,16,23, 4,11,16,23,
    6,10,15,21, 6,10,15,21, 6,10,15,21, 6,10,15,21 };

__constant__ uint8_t cG[64] = {
    0,1,2,3,4,5,6,7,8,9,10,11,12,13,14,15,
    1,6,11,0,5,10,15,4,9,14,3,8,13,2,7,12,
    5,8,11,14,1,4,7,10,13,0,3,6,9,12,15,2,
    0,7,14,5,12,3,10,1,8,15,6,13,4,11,2,9 };

// ---- f32 soft ops, exact IEEE-RN, reference association --------------------
__device__ __forceinline__ float fxor(float a, float b) {
    return __fsub_rn(__fadd_rn(a, b), __fmul_rn(__fmul_rn(2.0f, a), b));
}
__device__ __forceinline__ float fand(float a, float b) { return __fmul_rn(a, b); }
__device__ __forceinline__ float forr(float a, float b) {
    return __fsub_rn(__fadd_rn(a, b), __fmul_rn(a, b));
}
__device__ __forceinline__ float fnot(float a) { return __fsub_rn(1.0f, a); }

// state code: bit0 = hard bit, bit1 = deficit (value 1-2^-24)
__device__ __forceinline__ float decst(int st) {
    if (!(st & 1)) return 0.0f;
    return (st & 2) ? __uint_as_float(0x3F7FFFFFu) : 1.0f;
}
__device__ __forceinline__ float fphase(int ph, float b, float c, float d) {
    if (ph == 0) return forr(fand(b, c), fand(fnot(b), d));
    if (ph == 1) return forr(fand(d, b), fand(fnot(d), c));
    if (ph == 2) return fxor(fxor(b, c), d);
    return fxor(c, forr(b, fnot(d)));
}
// deficit predicate: soft_add32 result bit is (1-2^-24) iff hard=1 AND this
__device__ __forceinline__ uint32_t pbit(float x, float y) {
    float px = __fmul_rn(fxor(x, y), 0.5f);
    float r  = __fsub_rn(__fadd_rn(1.0f, px), px);
    return (__float_as_uint(r) != 0x3F800000u) ? 1u : 0u;
}

// ---- RN to 53-bit significand (RNE) of u64; inputs < 2^57 ------------------
__device__ __forceinline__ uint64_t rn53(uint64_t x) {
    uint32_t hi = (uint32_t)(x >> 32);
    int sh = 11 - __clz(hi);          // x < 2^53 -> sh <= 0 (clz(0)=32)
    if (sh > 0) {
        uint64_t keep = x >> sh;
        uint64_t half = 1ull << (sh - 1);
        uint64_t rem  = x & ((half << 1) - 1ull);
        keep += (rem > half) || ((rem == half) && (keep & 1ull));
        x = keep << sh;
    }
    return x;
}
// sequential f64 value of a T-valued word, 2^-24 units (R3-validated)
__device__ __forceinline__ uint64_t tvalm(uint32_t H, uint32_t P) {
    uint64_t E = (((uint64_t)(H & 0x1FFFFFFFu)) << 24) - (uint64_t)(P & 0x1FFFFFFFu);
#pragma unroll
    for (int i = 29; i < 32; i++) {
        uint64_t t = (((uint64_t)((H >> i) & 1u)) << (24 + i)) -
                     (((uint64_t)((P >> i) & 1u)) << i);
        E = rn53(E + t);
    }
    return E;
}
// spread nibble q of x into byte lanes (bit0 of each byte)
__device__ __forceinline__ uint32_t spread4(uint32_t x, int q) {
    return (((x >> (4 * q)) & 0xFu) * 0x00204081u) & 0x01010101u;
}
// gather bit k of each byte of Y[0..7] into a 32-bit mask
__device__ __forceinline__ uint32_t gatherk(const uint32_t* Y, int k) {
    uint32_t m = 0;
#pragma unroll
    for (int q = 0; q < 8; q++) {
        uint32_t t = (Y[q] >> k) & 0x01010101u;
        m |= (((t * 0x01020408u) >> 24) & 0xFu) << (4 * q);
    }
    return m;
}

#define C2P55 36028797018963968.0   // 2^55

// ---- one MD5 compress over byte-packed T-state ------------------------------
template<int BLK2>
__device__ void compress_fn(
    uint32_t& Ha, uint32_t& Pa, uint64_t& va,
    uint32_t& Hb, uint32_t& Pb, uint64_t& vb,
    uint32_t& Hc, uint32_t& Pc, uint64_t& vc,
    uint32_t& Hd, uint32_t& Pd, uint64_t& vd,
    const uint64_t* sTbl,
    const double* wvr, const uint32_t* m0, const uint32_t* x1, const uint32_t* x2)
{
    // byte-packed state: byte j = b2 | c2<<2 | d2<<4 | a2<<6
    uint32_t Y[8];
#pragma unroll
    for (int q = 0; q < 8; q++) {
        Y[q] = spread4(Hb,q)        | (spread4(Pb,q) << 1)
             | (spread4(Hc,q) << 2) | (spread4(Pc,q) << 3)
             | (spread4(Hd,q) << 4) | (spread4(Pd,q) << 5)
             | (spread4(Ha,q) << 6) | (spread4(Pa,q) << 7);
    }
    uint32_t HB = Hb, PB = Pb;

#pragma unroll 1
    for (int i = 0; i < 64; i++) {
        const uint64_t* ft = sTbl + ((i >> 4) << 8);
        double r = 0.0;
        uint32_t pred1 = 0;
#pragma unroll
        for (int j = 0; j < 32; j++) {
            uint32_t B = (Y[j >> 2] >> (8 * (j & 3))) & 0xFFu;
            uint64_t e = ft[B];
            pred1 |= ((uint32_t)e & 1u) << j;
            // r = fl(r*0.5 + f): scale-invariant form of s = fl(s + f*2^j)
            r = __fma_rn(r, 0.5, __longlong_as_double((long long)(e & ~1ull)));
        }
        // add1: f-sum + a    (fine x T; all in 2^-24 units)
        double sv = __fma_rn(r, C2P55, __ull2double_rn(va));   // exact product+RN
        uint32_t H1 = (uint32_t)(__double2ull_rz(sv) >> 24);
        uint32_t P1 = H1 & pred1;
        uint64_t v1 = tvalm(H1, P1);
        // add2: + K[i]   (T x hard, integer)
        uint32_t Km = cK[i];
        uint32_t H2 = (uint32_t)(rn53(v1 + (((uint64_t)Km) << 24)) >> 24);
        uint32_t P2 = H2 & (Km & P1);
        uint64_t v2 = tvalm(H2, P2);
        // add3: + word[g]
        int g = cG[i];
        uint32_t H3, P3;
        if (BLK2) {
            uint64_t pw  = (g == 0) ? (0x80ull << 24) : ((g == 14) ? (0x200ull << 24) : 0ull);
            uint32_t pwm = (g == 0) ? 0x80u : ((g == 14) ? 0x200u : 0u);
            H3 = (uint32_t)(rn53(v2 + pw) >> 24);
            P3 = H3 & (P2 & pwm);
        } else {
            double s3 = __fma_rn(wvr[g], C2P55, __ull2double_rn(v2));
            H3 = (uint32_t)(__double2ull_rz(s3) >> 24);
            uint32_t pr = m0[g] ^ (H2 & x1[g]) ^ (P2 & x2[g]);
            P3 = H3 & pr;
        }
        // rotate, then b = soft_add32(b, rot)   (T x T, integer)
        int sh = cS[i];
        uint32_t H3r = __funnelshift_l(H3, H3, sh);
        uint32_t P3r = __funnelshift_l(P3, P3, sh);
        uint64_t v3 = tvalm(H3r, P3r);
        uint32_t H4 = (uint32_t)(rn53(vb + v3) >> 24);
        uint32_t P4 = H4 & (HB & H3r & (PB | P3r));
        uint64_t v4 = tvalm(H4, P4);
        // state rotation: bytes shift b->c->d->a; insert new b
#pragma unroll
        for (int q = 0; q < 8; q++) {
            uint32_t bb = spread4(H4, q) | (spread4(P4, q) << 1);
            Y[q] = ((Y[q] & 0x3F3F3F3Fu) << 2) | bb;
        }
        va = vd; vd = vc; vc = vb; vb = v4;
        HB = H4; PB = P4;
    }
    // recover final masks from Y
    Hb = HB;           Pb = PB;
    Hc = gatherk(Y,2); Pc = gatherk(Y,3);
    Hd = gatherk(Y,4); Pd = gatherk(Y,5);
    Ha = gatherk(Y,6); Pa = gatherk(Y,7);
}

// T (+) T soft_add32 on masks (alias-safe)
__device__ __forceinline__ void tadd(uint32_t Hx, uint32_t Px, uint64_t vx,
                                     uint32_t Hy, uint32_t Py, uint64_t vy,
                                     uint32_t& Ho, uint32_t& Po, uint64_t& vo) {
    uint32_t ho = (uint32_t)(rn53(vx + vy) >> 24);
    uint32_t po = ho & (Hx & Hy & (Px | Py));
    uint64_t vv = tvalm(ho, po);
    Ho = ho; Po = po; vo = vv;
}

__global__ void __launch_bounds__(TPB)
softmd5_kernel(const float* __restrict__ in, float* __restrict__ out, int B)
{
    // 4 phases x 256 entries: f64(f) with pred(idx, ast) stolen into bit0
    __shared__ uint64_t sTbl[4 * 256];

    int t = threadIdx.x;
    for (int k = t; k < 1024; k += TPB) {
        int ph = k >> 8, Bc = k & 255;
        float b = decst(Bc & 3), c = decst((Bc >> 2) & 3), d = decst((Bc >> 4) & 3);
        float a = decst((Bc >> 6) & 3);
        float f = fphase(ph, b, c, d);
        uint64_t bits = (uint64_t)__double_as_longlong((double)f);  // 29 low zeros
        sTbl[k] = (bits & ~1ull) | pbit(f, a);
    }
    __syncthreads();

    int row = blockIdx.x * TPB + t;
    if (row >= B) return;

    const float4* rp = reinterpret_cast<const float4*>(in + (size_t)row * 512);
    const float ONEME = __uint_as_float(0x3F7FFFFFu);

    // word values: r-chain (scale 2^-31 of the reference f64 chain) + masks
    double   wvr[16];
    uint32_t m0[16], x1[16], x2[16];
#pragma unroll 1
    for (int g = 0; g < 16; g++) {
        double r = 0.0;
        uint32_t a0 = 0, a1 = 0, a2 = 0;
        for (int q = 0; q < 8; q++) {
            float4 w4 = rp[g * 8 + q];
            float w[4] = { w4.x, w4.y, w4.z, w4.w };
#pragma unroll
            for (int u = 0; u < 4; u++) {
                int j = q * 4 + u;
                r = __fma_rn(r, 0.5, (double)w[u]);
                a0 |= pbit(0.0f,  w[u]) << j;
                a1 |= pbit(1.0f,  w[u]) << j;
                a2 |= pbit(ONEME, w[u]) << j;
            }
        }
        wvr[g] = r; m0[g] = a0; x1[g] = a0 ^ a1; x2[g] = a1 ^ a2;
    }

    // H-state (T-masks + cached value, 2^-24 units u64)
    uint32_t HA = 0x67452301u, PA = 0, HB = 0xefcdab89u, PB = 0;
    uint32_t HC = 0x98badcfeu, PC = 0, HD = 0x10325476u, PD = 0;
    uint64_t VA = ((uint64_t)HA) << 24, VB = ((uint64_t)HB) << 24;
    uint64_t VC = ((uint64_t)HC) << 24, VD = ((uint64_t)HD) << 24;

    // ---- block 1 ----
    {
        uint32_t ha=HA,pa=PA,hb=HB,pb=PB,hc=HC,pc=PC,hd=HD,pd=PD;
        uint64_t va=VA,vb=VB,vc=VC,vd=VD;
        compress_fn<0>(ha,pa,va, hb,pb,vb, hc,pc,vc, hd,pd,vd,
                       sTbl, wvr, m0, x1, x2);
        tadd(HA,PA,VA, ha,pa,va, HA,PA,VA);
        tadd(HB,PB,VB, hb,pb,vb, HB,PB,VB);
        tadd(HC,PC,VC, hc,pc,vc, HC,PC,VC);
        tadd(HD,PD,VD, hd,pd,vd, HD,PD,VD);
    }
    // ---- block 2 (constant padding) ----
    {
        uint32_t ha=HA,pa=PA,hb=HB,pb=PB,hc=HC,pc=PC,hd=HD,pd=PD;
        uint64_t va=VA,vb=VB,vc=VC,vd=VD;
        compress_fn<1>(ha,pa,va, hb,pb,vb, hc,pc,vc, hd,pd,vd,
                       sTbl, wvr, m0, x1, x2);
        tadd(HA,PA,VA, ha,pa,va, HA,PA,VA);
        tadd(HB,PB,VB, hb,pb,vb, HB,PB,VB);
        tadd(HC,PC,VC, hc,pc,vc, HC,PC,VC);
        tadd(HD,PD,VD, hd,pd,vd, HD,PD,VD);
    }

    // ---- emit 128 float bits ----
    float4* op = reinterpret_cast<float4*>(out + (size_t)row * 128);
    uint32_t Hs[4] = { HA, HB, HC, HD }, Ps[4] = { PA, PB, PC, PD };
#pragma unroll
    for (int w = 0; w < 4; w++) {
        uint32_t Hm = Hs[w], Pm = Ps[w];
#pragma unroll
        for (int j = 0; j < 32; j += 4) {
            float4 f4;
            f4.x = __uint_as_float(((Hm>>(j+0))&1u) ? (((Pm>>(j+0))&1u)?0x3F7FFFFFu:0x3F800000u) : 0u);
            f4.y = __uint_as_float(((Hm>>(j+1))&1u) ? (((Pm>>(j+1))&1u)?0x3F7FFFFFu:0x3F800000u) : 0u);
            f4.z = __uint_as_float(((Hm>>(j+2))&1u) ? (((Pm>>(j+2))&1u)?0x3F7FFFFFu:0x3F800000u) : 0u);
            f4.w = __uint_as_float(((Hm>>(j+3))&1u) ? (((Pm>>(j+3))&1u)?0x3F7FFFFFu:0x3F800000u) : 0u);
            op[w*8 + (j>>2)] = f4;
        }
    }
}

extern "C" void kernel_launch(void* const* d_in, const int* in_sizes, int n_in,
                              void* d_out, int out_size)
{
    const float* in = (const float*)d_in[0];
    float* out = (float*)d_out;
    int B = in_sizes[0] / 512;            // 131072 rows
    int blocks = (B + TPB - 1) / TPB;
    softmd5_kernel<<<blocks, TPB>>>(in, out, B);
}